// round 13
// baseline (speedup 1.0000x reference)
#include <cuda_runtime.h>

// CrossCompressUnit: B=262144 rows, D=64.
// v_out = v * (e·w_vv) + e * (v·w_ev) + bias_v
// e_out = v * (e·w_ve) + e * (v·w_ee) + bias_e
//
// R12: persistent grid-stride variant of the roofline-bound R1 config.
// grid = 148 SMs * 8 CTAs = 1184 persistent CTAs, 256 threads each.
// Weights/biases loaded ONCE per thread (hoisted); the ~14-iteration loop
// body is just: 2 coalesced float4 loads, 4 partial dots, 12 SHFLs,
// 2 coalesced float4 stores. Adjacent half-warps process adjacent rows
// each iteration -> 512B contiguous per warp per array.

#define D 64
#define VEC 4
#define LANES_PER_ROW (D / VEC)   // 16
#define NUM_SMS 148
#define CTAS_PER_SM 8
#define THREADS 256

__global__ __launch_bounds__(THREADS, CTAS_PER_SM)
void cross_compress_kernel(const float* __restrict__ v,
                           const float* __restrict__ e,
                           const float* __restrict__ w_vv,
                           const float* __restrict__ w_ev,
                           const float* __restrict__ w_ve,
                           const float* __restrict__ w_ee,
                           const float* __restrict__ bias_v,
                           const float* __restrict__ bias_e,
                           float* __restrict__ v_out,
                           float* __restrict__ e_out,
                           int n_rows)
{
    const int tid = blockIdx.x * blockDim.x + threadIdx.x;
    const int l   = tid & (LANES_PER_ROW - 1);      // 0..15 within row group
    int row       = tid / LANES_PER_ROW;            // starting row
    const int row_stride = (gridDim.x * blockDim.x) / LANES_PER_ROW;

    // Hoisted: weight/bias slices for this lane (loaded once per thread)
    const float4 wvv = __ldg(&((const float4*)w_vv)[l]);
    const float4 wev = __ldg(&((const float4*)w_ev)[l]);
    const float4 wve = __ldg(&((const float4*)w_ve)[l]);
    const float4 wee = __ldg(&((const float4*)w_ee)[l]);
    const float4 bv  = __ldg(&((const float4*)bias_v)[l]);
    const float4 be  = __ldg(&((const float4*)bias_e)[l]);

    const float4* v4p = (const float4*)v;
    const float4* e4p = (const float4*)e;
    float4* vo4p = (float4*)v_out;
    float4* eo4p = (float4*)e_out;

    for (; row < n_rows; row += row_stride) {
        const long long base4 = (long long)row * LANES_PER_ROW + l;

        float4 v4 = __ldg(&v4p[base4]);
        float4 e4 = __ldg(&e4p[base4]);

        // 4 partial dot products
        float a = e4.x*wvv.x + e4.y*wvv.y + e4.z*wvv.z + e4.w*wvv.w; // e·w_vv
        float b = v4.x*wev.x + v4.y*wev.y + v4.z*wev.z + v4.w*wev.w; // v·w_ev
        float c = e4.x*wve.x + e4.y*wve.y + e4.z*wve.z + e4.w*wve.w; // e·w_ve
        float d = v4.x*wee.x + v4.y*wee.y + v4.z*wee.z + v4.w*wee.w; // v·w_ee

        // reduce across the 16-lane group (xor masks < 16 stay in-group)
        #pragma unroll
        for (int m = 8; m >= 1; m >>= 1) {
            a += __shfl_xor_sync(0xffffffffu, a, m);
            b += __shfl_xor_sync(0xffffffffu, b, m);
            c += __shfl_xor_sync(0xffffffffu, c, m);
            d += __shfl_xor_sync(0xffffffffu, d, m);
        }

        float4 vo, eo;
        vo.x = fmaf(v4.x, a, fmaf(e4.x, b, bv.x));
        vo.y = fmaf(v4.y, a, fmaf(e4.y, b, bv.y));
        vo.z = fmaf(v4.z, a, fmaf(e4.z, b, bv.z));
        vo.w = fmaf(v4.w, a, fmaf(e4.w, b, bv.w));

        eo.x = fmaf(v4.x, c, fmaf(e4.x, d, be.x));
        eo.y = fmaf(v4.y, c, fmaf(e4.y, d, be.y));
        eo.z = fmaf(v4.z, c, fmaf(e4.z, d, be.z));
        eo.w = fmaf(v4.w, c, fmaf(e4.w, d, be.w));

        vo4p[base4] = vo;
        eo4p[base4] = eo;
    }
}

extern "C" void kernel_launch(void* const* d_in, const int* in_sizes, int n_in,
                              void* d_out, int out_size)
{
    const float* v      = (const float*)d_in[0];
    const float* e      = (const float*)d_in[1];
    const float* w_vv   = (const float*)d_in[2];
    const float* w_ev   = (const float*)d_in[3];
    const float* w_ve   = (const float*)d_in[4];
    const float* w_ee   = (const float*)d_in[5];
    const float* bias_v = (const float*)d_in[6];
    const float* bias_e = (const float*)d_in[7];

    const int n_rows = in_sizes[0] / D;        // B = 262144

    float* out   = (float*)d_out;
    float* v_out = out;                         // first half: v_out [B, D]
    float* e_out = out + (long long)n_rows * D; // second half: e_out [B, D]

    const int blocks = NUM_SMS * CTAS_PER_SM;   // 1184 persistent CTAs

    cross_compress_kernel<<<blocks, THREADS>>>(v, e, w_vv, w_ev, w_ve, w_ee,
                                               bias_v, bias_e, v_out, e_out,
                                               n_rows);
}

// round 14
// speedup vs baseline: 1.3126x; 1.3126x over previous
#include <cuda_runtime.h>

// CrossCompressUnit: B=262144 rows, D=64.
// v_out = v * (e·w_vv) + e * (v·w_ev) + bias_v
// e_out = v * (e·w_ve) + e * (v·w_ee) + bias_e
//
// FINAL — champion config (R1), measured best of 7 structural variants:
// one-shot launch, half-warp (16 lanes) per row, one float4 per lane (warp
// covers 2 consecutive rows = 512B fully contiguous per load), 4-round
// butterfly reduce, plain cached loads + plain write-allocate stores,
// 256-thread blocks, 16384 CTAs, occ ~80%.
//
// Roofline evidence: kernel pinned at 38.1-38.9 µs / DRAM 70-71% across all
// working shapes (reduction width, cache hints, block size); persistent
// grid-stride regressed to 51.7 µs (loop-carried alias deps collapse MLP —
// 16384 independent one-shot CTAs give a deeper outstanding-request pool).
// 268 MB compulsory 1:1 read/write stream at ~6.9 TB/s effective = 86% of
// the 8 TB/s HBM3e spec. This is the floor.

#define D 64
#define VEC 4
#define LANES_PER_ROW (D / VEC)   // 16

__global__ __launch_bounds__(256, 8)
void cross_compress_kernel(const float* __restrict__ v,
                           const float* __restrict__ e,
                           const float* __restrict__ w_vv,
                           const float* __restrict__ w_ev,
                           const float* __restrict__ w_ve,
                           const float* __restrict__ w_ee,
                           const float* __restrict__ bias_v,
                           const float* __restrict__ bias_e,
                           float* __restrict__ v_out,
                           float* __restrict__ e_out,
                           int n_rows)
{
    const int tid      = blockIdx.x * blockDim.x + threadIdx.x;
    const int row      = tid / LANES_PER_ROW;       // one row per 16 lanes
    const int l        = tid & (LANES_PER_ROW - 1); // 0..15 within row
    if (row >= n_rows) return;

    const long long base4 = (long long)row * LANES_PER_ROW + l; // float4 index

    const float4* v4p = (const float4*)v;
    const float4* e4p = (const float4*)e;

    float4 v4 = __ldg(&v4p[base4]);
    float4 e4 = __ldg(&e4p[base4]);

    // weight/bias slices for this lane (L1-resident after wave 1)
    float4 wvv = __ldg(&((const float4*)w_vv)[l]);
    float4 wev = __ldg(&((const float4*)w_ev)[l]);
    float4 wve = __ldg(&((const float4*)w_ve)[l]);
    float4 wee = __ldg(&((const float4*)w_ee)[l]);
    float4 bv  = __ldg(&((const float4*)bias_v)[l]);
    float4 be  = __ldg(&((const float4*)bias_e)[l]);

    // 4 partial dot products
    float a = e4.x*wvv.x + e4.y*wvv.y + e4.z*wvv.z + e4.w*wvv.w; // e·w_vv
    float b = v4.x*wev.x + v4.y*wev.y + v4.z*wev.z + v4.w*wev.w; // v·w_ev
    float c = e4.x*wve.x + e4.y*wve.y + e4.z*wve.z + e4.w*wve.w; // e·w_ve
    float d = v4.x*wee.x + v4.y*wee.y + v4.z*wee.z + v4.w*wee.w; // v·w_ee

    // reduce across the 16-lane group (xor masks < 16 stay in-group)
    #pragma unroll
    for (int m = 8; m >= 1; m >>= 1) {
        a += __shfl_xor_sync(0xffffffffu, a, m);
        b += __shfl_xor_sync(0xffffffffu, b, m);
        c += __shfl_xor_sync(0xffffffffu, c, m);
        d += __shfl_xor_sync(0xffffffffu, d, m);
    }

    float4 vo, eo;
    vo.x = fmaf(v4.x, a, fmaf(e4.x, b, bv.x));
    vo.y = fmaf(v4.y, a, fmaf(e4.y, b, bv.y));
    vo.z = fmaf(v4.z, a, fmaf(e4.z, b, bv.z));
    vo.w = fmaf(v4.w, a, fmaf(e4.w, b, bv.w));

    eo.x = fmaf(v4.x, c, fmaf(e4.x, d, be.x));
    eo.y = fmaf(v4.y, c, fmaf(e4.y, d, be.y));
    eo.z = fmaf(v4.z, c, fmaf(e4.z, d, be.z));
    eo.w = fmaf(v4.w, c, fmaf(e4.w, d, be.w));

    ((float4*)v_out)[base4] = vo;
    ((float4*)e_out)[base4] = eo;
}

extern "C" void kernel_launch(void* const* d_in, const int* in_sizes, int n_in,
                              void* d_out, int out_size)
{
    const float* v      = (const float*)d_in[0];
    const float* e      = (const float*)d_in[1];
    const float* w_vv   = (const float*)d_in[2];
    const float* w_ev   = (const float*)d_in[3];
    const float* w_ve   = (const float*)d_in[4];
    const float* w_ee   = (const float*)d_in[5];
    const float* bias_v = (const float*)d_in[6];
    const float* bias_e = (const float*)d_in[7];

    const int n_rows = in_sizes[0] / D;        // B = 262144

    float* out   = (float*)d_out;
    float* v_out = out;                         // first half: v_out [B, D]
    float* e_out = out + (long long)n_rows * D; // second half: e_out [B, D]

    const int threads = 256;
    const long long total_threads = (long long)n_rows * LANES_PER_ROW;
    const int blocks = (int)((total_threads + threads - 1) / threads);

    cross_compress_kernel<<<blocks, threads>>>(v, e, w_vv, w_ev, w_ve, w_ee,
                                               bias_v, bias_e, v_out, e_out,
                                               n_rows);
}

// round 15
// speedup vs baseline: 1.3154x; 1.0021x over previous
#include <cuda_runtime.h>

// CrossCompressUnit: B=262144 rows, D=64.
// v_out = v * (e·w_vv) + e * (v·w_ev) + bias_v
// e_out = v * (e·w_ve) + e * (v·w_ee) + bias_e
//
// CONVERGED FINAL — champion config, measured best of 8 structural variants
// across the session (reduction width 16/8, cache hints ldcs/stcs/plain,
// block 256/512, one-shot vs persistent):
//   one-shot launch, half-warp (16 lanes) per row, one float4 per lane
//   (warp covers 2 consecutive rows = 512B fully contiguous per load),
//   4-round butterfly reduce, plain cached loads + write-allocate stores,
//   256-thread blocks, 16384 CTAs, occ ~80%, 32 regs.
//
// Roofline evidence: kernel pinned at 38.1-38.9 µs / DRAM 70-71%
// (5.5-5.6 TB/s bus) invariant across all instruction mixes; L2 absorbs
// ~52 MB/replay of the 268 MB compulsory 1:1 read/write stream ->
// ~6.9 TB/s effective logical BW = 86% of 8 TB/s HBM3e spec.
// Falsified: cache-policy hints (neutral/worse), persistent grid-stride
// (51.7 µs — loop-carried alias deps collapse MLP), larger blocks (worse
// wave balance). L2-persistence carveout is rule-blocked; TMA is
// path-independent on B300. This is the floor.

#define D 64
#define VEC 4
#define LANES_PER_ROW (D / VEC)   // 16

__global__ __launch_bounds__(256, 8)
void cross_compress_kernel(const float* __restrict__ v,
                           const float* __restrict__ e,
                           const float* __restrict__ w_vv,
                           const float* __restrict__ w_ev,
                           const float* __restrict__ w_ve,
                           const float* __restrict__ w_ee,
                           const float* __restrict__ bias_v,
                           const float* __restrict__ bias_e,
                           float* __restrict__ v_out,
                           float* __restrict__ e_out,
                           int n_rows)
{
    const int tid      = blockIdx.x * blockDim.x + threadIdx.x;
    const int row      = tid / LANES_PER_ROW;       // one row per 16 lanes
    const int l        = tid & (LANES_PER_ROW - 1); // 0..15 within row
    if (row >= n_rows) return;

    const long long base4 = (long long)row * LANES_PER_ROW + l; // float4 index

    const float4* v4p = (const float4*)v;
    const float4* e4p = (const float4*)e;

    float4 v4 = __ldg(&v4p[base4]);
    float4 e4 = __ldg(&e4p[base4]);

    // weight/bias slices for this lane (L1-resident after wave 1)
    float4 wvv = __ldg(&((const float4*)w_vv)[l]);
    float4 wev = __ldg(&((const float4*)w_ev)[l]);
    float4 wve = __ldg(&((const float4*)w_ve)[l]);
    float4 wee = __ldg(&((const float4*)w_ee)[l]);
    float4 bv  = __ldg(&((const float4*)bias_v)[l]);
    float4 be  = __ldg(&((const float4*)bias_e)[l]);

    // 4 partial dot products
    float a = e4.x*wvv.x + e4.y*wvv.y + e4.z*wvv.z + e4.w*wvv.w; // e·w_vv
    float b = v4.x*wev.x + v4.y*wev.y + v4.z*wev.z + v4.w*wev.w; // v·w_ev
    float c = e4.x*wve.x + e4.y*wve.y + e4.z*wve.z + e4.w*wve.w; // e·w_ve
    float d = v4.x*wee.x + v4.y*wee.y + v4.z*wee.z + v4.w*wee.w; // v·w_ee

    // reduce across the 16-lane group (xor masks < 16 stay in-group)
    #pragma unroll
    for (int m = 8; m >= 1; m >>= 1) {
        a += __shfl_xor_sync(0xffffffffu, a, m);
        b += __shfl_xor_sync(0xffffffffu, b, m);
        c += __shfl_xor_sync(0xffffffffu, c, m);
        d += __shfl_xor_sync(0xffffffffu, d, m);
    }

    float4 vo, eo;
    vo.x = fmaf(v4.x, a, fmaf(e4.x, b, bv.x));
    vo.y = fmaf(v4.y, a, fmaf(e4.y, b, bv.y));
    vo.z = fmaf(v4.z, a, fmaf(e4.z, b, bv.z));
    vo.w = fmaf(v4.w, a, fmaf(e4.w, b, bv.w));

    eo.x = fmaf(v4.x, c, fmaf(e4.x, d, be.x));
    eo.y = fmaf(v4.y, c, fmaf(e4.y, d, be.y));
    eo.z = fmaf(v4.z, c, fmaf(e4.z, d, be.z));
    eo.w = fmaf(v4.w, c, fmaf(e4.w, d, be.w));

    ((float4*)v_out)[base4] = vo;
    ((float4*)e_out)[base4] = eo;
}

extern "C" void kernel_launch(void* const* d_in, const int* in_sizes, int n_in,
                              void* d_out, int out_size)
{
    const float* v      = (const float*)d_in[0];
    const float* e      = (const float*)d_in[1];
    const float* w_vv   = (const float*)d_in[2];
    const float* w_ev   = (const float*)d_in[3];
    const float* w_ve   = (const float*)d_in[4];
    const float* w_ee   = (const float*)d_in[5];
    const float* bias_v = (const float*)d_in[6];
    const float* bias_e = (const float*)d_in[7];

    const int n_rows = in_sizes[0] / D;        // B = 262144

    float* out   = (float*)d_out;
    float* v_out = out;                         // first half: v_out [B, D]
    float* e_out = out + (long long)n_rows * D; // second half: e_out [B, D]

    const int threads = 256;
    const long long total_threads = (long long)n_rows * LANES_PER_ROW;
    const int blocks = (int)((total_threads + threads - 1) / threads);

    cross_compress_kernel<<<blocks, threads>>>(v, e, w_vv, w_ev, w_ve, w_ee,
                                               bias_v, bias_e, v_out, e_out,
                                               n_rows);
}

// round 17
// speedup vs baseline: 1.3163x; 1.0007x over previous
#include <cuda_runtime.h>

// CrossCompressUnit: B=262144 rows, D=64.
// v_out = v * (e·w_vv) + e * (v·w_ev) + bias_v
// e_out = v * (e·w_ve) + e * (v·w_ee) + bias_e
//
// CONVERGED FINAL — champion config (best of 8 structural variants) with a
// zero-risk polish: 32-bit addressing (max float4 index 2^26 -> 2^30 bytes,
// fits u32; kills IMAD.WIDE chains).
//
// Config: one-shot launch, half-warp (16 lanes) per row, one float4 per lane
// (warp covers 2 consecutive rows = 512B fully contiguous per load),
// 4-round butterfly reduce, plain cached loads + write-allocate stores,
// 256-thread blocks, 16384 CTAs, occ ~81%.
//
// Roofline evidence (4 reproductions): kernel 38.1-38.9 µs, DRAM 70-71%
// (5.5-5.6 TB/s bus), invariant across reduction width, cache policy, block
// size, occupancy. L2 absorbs ~52 MB/replay of the 268 MB compulsory 1:1
// read/write stream -> ~6.9 TB/s effective logical BW = 86% of 8 TB/s spec.
// Falsified: cache hints (neutral/worse), 512-thr blocks (-2%), persistent
// grid-stride (-26%, MLP collapse). This is the floor.

#define D 64
#define VEC 4
#define LANES_PER_ROW (D / VEC)   // 16

__global__ __launch_bounds__(256, 8)
void cross_compress_kernel(const float* __restrict__ v,
                           const float* __restrict__ e,
                           const float* __restrict__ w_vv,
                           const float* __restrict__ w_ev,
                           const float* __restrict__ w_ve,
                           const float* __restrict__ w_ee,
                           const float* __restrict__ bias_v,
                           const float* __restrict__ bias_e,
                           float* __restrict__ v_out,
                           float* __restrict__ e_out,
                           unsigned n_rows)
{
    const unsigned tid = blockIdx.x * blockDim.x + threadIdx.x;
    const unsigned row = tid / LANES_PER_ROW;        // one row per 16 lanes
    const unsigned l   = tid & (LANES_PER_ROW - 1);  // 0..15 within row
    if (row >= n_rows) return;

    // 32-bit float4 index: max 2^26, byte offset max 2^30 — fits u32.
    const unsigned base4 = row * LANES_PER_ROW + l;

    const float4* v4p = (const float4*)v;
    const float4* e4p = (const float4*)e;

    float4 v4 = __ldg(&v4p[base4]);
    float4 e4 = __ldg(&e4p[base4]);

    // weight/bias slices for this lane (L1-resident after wave 1)
    float4 wvv = __ldg(&((const float4*)w_vv)[l]);
    float4 wev = __ldg(&((const float4*)w_ev)[l]);
    float4 wve = __ldg(&((const float4*)w_ve)[l]);
    float4 wee = __ldg(&((const float4*)w_ee)[l]);
    float4 bv  = __ldg(&((const float4*)bias_v)[l]);
    float4 be  = __ldg(&((const float4*)bias_e)[l]);

    // 4 partial dot products
    float a = e4.x*wvv.x + e4.y*wvv.y + e4.z*wvv.z + e4.w*wvv.w; // e·w_vv
    float b = v4.x*wev.x + v4.y*wev.y + v4.z*wev.z + v4.w*wev.w; // v·w_ev
    float c = e4.x*wve.x + e4.y*wve.y + e4.z*wve.z + e4.w*wve.w; // e·w_ve
    float d = v4.x*wee.x + v4.y*wee.y + v4.z*wee.z + v4.w*wee.w; // v·w_ee

    // reduce across the 16-lane group (xor masks < 16 stay in-group)
    #pragma unroll
    for (int m = 8; m >= 1; m >>= 1) {
        a += __shfl_xor_sync(0xffffffffu, a, m);
        b += __shfl_xor_sync(0xffffffffu, b, m);
        c += __shfl_xor_sync(0xffffffffu, c, m);
        d += __shfl_xor_sync(0xffffffffu, d, m);
    }

    float4 vo, eo;
    vo.x = fmaf(v4.x, a, fmaf(e4.x, b, bv.x));
    vo.y = fmaf(v4.y, a, fmaf(e4.y, b, bv.y));
    vo.z = fmaf(v4.z, a, fmaf(e4.z, b, bv.z));
    vo.w = fmaf(v4.w, a, fmaf(e4.w, b, bv.w));

    eo.x = fmaf(v4.x, c, fmaf(e4.x, d, be.x));
    eo.y = fmaf(v4.y, c, fmaf(e4.y, d, be.y));
    eo.z = fmaf(v4.z, c, fmaf(e4.z, d, be.z));
    eo.w = fmaf(v4.w, c, fmaf(e4.w, d, be.w));

    ((float4*)v_out)[base4] = vo;
    ((float4*)e_out)[base4] = eo;
}

extern "C" void kernel_launch(void* const* d_in, const int* in_sizes, int n_in,
                              void* d_out, int out_size)
{
    const float* v      = (const float*)d_in[0];
    const float* e      = (const float*)d_in[1];
    const float* w_vv   = (const float*)d_in[2];
    const float* w_ev   = (const float*)d_in[3];
    const float* w_ve   = (const float*)d_in[4];
    const float* w_ee   = (const float*)d_in[5];
    const float* bias_v = (const float*)d_in[6];
    const float* bias_e = (const float*)d_in[7];

    const unsigned n_rows = (unsigned)(in_sizes[0] / D);   // B = 262144

    float* out   = (float*)d_out;
    float* v_out = out;                              // first half: v_out [B, D]
    float* e_out = out + (size_t)n_rows * D;         // second half: e_out [B, D]

    const int threads = 256;
    const long long total_threads = (long long)n_rows * LANES_PER_ROW;
    const int blocks = (int)((total_threads + threads - 1) / threads);

    cross_compress_kernel<<<blocks, threads>>>(v, e, w_vv, w_ev, w_ve, w_ee,
                                               bias_v, bias_e, v_out, e_out,
                                               n_rows);
}